// round 13
// baseline (speedup 1.0000x reference)
#include <cuda_runtime.h>
#include <math_constants.h>
#include <cstdint>

#define SB 16
#define SS 577
#define DD 768
#define HH 12
#define HD 64
#define MTOT (SB*SS)
#define BST 580          // padded bias row stride
#define VPD 584          // padded seq stride for transposed V (mult of 4)

// projection GEMM tiling
#define BM 128
#define BN 128
#define BK 32
#define NKC (DD/BK)      // 24
#define ASTR 36          // padded smem row stride (floats) — bank stride 4
#define STG_FLOATS ((BM+BN)*ASTR)          // 9216
#define STG_BYTES  (STG_FLOATS*4u)         // 36864
#define PROJ_SMEM  (3u*STG_BYTES)          // 110592

// attention tiling
#define KST 68           // K / V^T / P-bias smem stride — bank stride 4
#define ATTN_SMEM ((64*KST*3) * 4)         // 52224 B

__device__ float g_q[(size_t)SB*HH*SS*HD];
__device__ float g_k[(size_t)SB*HH*SS*HD];
__device__ float g_v[(size_t)SB*HH*HD*VPD];   // transposed: [b,h,d,s]
__device__ float g_xr[(size_t)MTOT*DD];
__device__ float g_wt[(size_t)3*DD*DD];
__device__ float g_bias[(size_t)HH*SS*BST];

__device__ __forceinline__ uint32_t tf32r(float x){
    uint32_t o; asm("cvt.rna.tf32.f32 %0, %1;" : "=r"(o) : "f"(x));
    return o;
}
__device__ __forceinline__ uint32_t smem_u32(const void* p){
    uint32_t a;
    asm("{ .reg .u64 t; cvta.to.shared.u64 t, %1; cvt.u32.u64 %0, t; }" : "=r"(a) : "l"(p));
    return a;
}
__device__ __forceinline__ void cpa16(uint32_t dst, const float* src, bool valid){
    int sz = valid ? 16 : 0;
    asm volatile("cp.async.cg.shared.global [%0], [%1], 16, %2;" :: "r"(dst), "l"(src), "r"(sz));
}
__device__ __forceinline__ void ldsm4(uint32_t* r, uint32_t addr){
    asm volatile("ldmatrix.sync.aligned.m8n8.x4.shared.b16 {%0,%1,%2,%3}, [%4];"
        : "=r"(r[0]), "=r"(r[1]), "=r"(r[2]), "=r"(r[3]) : "r"(addr));
}
__device__ __forceinline__ void mma_tf32(float* c, const uint32_t* a, const uint32_t* b){
    asm volatile(
        "mma.sync.aligned.m16n8k8.row.col.f32.tf32.tf32.f32 "
        "{%0,%1,%2,%3}, {%4,%5,%6,%7}, {%8,%9}, {%0,%1,%2,%3};"
        : "+f"(c[0]), "+f"(c[1]), "+f"(c[2]), "+f"(c[3])
        : "r"(a[0]), "r"(a[1]), "r"(a[2]), "r"(a[3]), "r"(b[0]), "r"(b[1]));
}

// ---------------- 1) bias gather (padded rows) ----------------
__global__ __launch_bounds__(256) void bias_kernel(const float* __restrict__ table,
                                                   const int* __restrict__ idx)
{
    int e = blockIdx.x * 256 + threadIdx.x;
    if (e >= SS * SS) return;
    int q = e / SS, k = e - q * SS;
    int i = idx[e];
    #pragma unroll
    for (int h = 0; h < HH; h++)
        g_bias[((size_t)h * SS + q) * BST + k] = table[i * HH + h];
}

// ---------------- 1b) pre-round X to tf32 ----------------
__global__ __launch_bounds__(256) void xround_kernel(const float* __restrict__ X)
{
    size_t i = ((size_t)blockIdx.x * 256 + threadIdx.x) * 4;
    if (i < (size_t)MTOT * DD) {
        float4 v = *(const float4*)&X[i];
        v.x = __uint_as_float(tf32r(v.x)); v.y = __uint_as_float(tf32r(v.y));
        v.z = __uint_as_float(tf32r(v.z)); v.w = __uint_as_float(tf32r(v.w));
        *(float4*)&g_xr[i] = v;
    }
}

// ---------------- 2) weight transpose (+ tf32 round) ----------------
__global__ void transpose_w(const float* __restrict__ Wq,
                            const float* __restrict__ Wk,
                            const float* __restrict__ Wv)
{
    __shared__ float t[32][33];
    int g = blockIdx.z;
    const float* W = (g == 0) ? Wq : (g == 1) ? Wk : Wv;
    int k0 = blockIdx.x * 32, n0 = blockIdx.y * 32;
    int tx = threadIdx.x, ty = threadIdx.y;
    #pragma unroll
    for (int i = 0; i < 32; i += 8)
        t[ty + i][tx] = W[(size_t)(k0 + ty + i) * DD + n0 + tx];
    __syncthreads();
    #pragma unroll
    for (int i = 0; i < 32; i += 8)
        g_wt[(size_t)g * DD * DD + (size_t)(n0 + ty + i) * DD + k0 + tx] =
            __uint_as_float(tf32r(t[tx][ty + i]));
}

// ---------------- 3) projection: 64x64 warp tiles, one-sync pipeline ----------------
__global__ __launch_bounds__(128) void proj_mma_kernel(
    const float* __restrict__ bq, const float* __restrict__ bv)
{
    extern __shared__ float smf[];
    const uint32_t s32 = smem_u32(smf);

    const int tid = threadIdx.x;
    const int wid = tid >> 5, lane = tid & 31;
    const int wm = (wid >> 1) * 64;
    const int wn = (wid & 1) * 64;
    const int g = lane >> 2, tg = lane & 3;

    const int m0 = blockIdx.x * BM;
    const int n0 = blockIdx.y * BN;
    const int which = blockIdx.z;
    const float* Wt   = g_wt + (size_t)which * DD * DD;
    const float* badd = (which == 0) ? bq : (which == 2) ? bv : nullptr;
    const float scl   = (which == 0) ? 0.125f : 1.0f;

    // ldmatrix lane address components
    const uint32_t a_row  = wm + (lane & 15);
    const uint32_t a_ksel = (uint32_t)(lane >> 4) << 2;
    const uint32_t aoff = (a_row * ASTR + a_ksel) * 4u;
    const uint32_t b_row  = wn + (lane & 7) + ((lane >> 4) << 3);
    const uint32_t b_ksel = (uint32_t)((lane >> 3) & 1) << 2;
    const uint32_t boff = (uint32_t)(BM * ASTR) * 4u + (b_row * ASTR + b_ksel) * 4u;

    #define ISSUE_STAGE(kc, stg)                                                     \
    {                                                                                \
        int kb = (kc) * BK;                                                          \
        uint32_t ab = s32 + (stg) * STG_BYTES;                                       \
        uint32_t bb = ab + BM * ASTR * 4u;                                           \
        _Pragma("unroll")                                                            \
        for (int i = 0; i < 8; i++) {                                                \
            int u = tid + i * 128;                                                   \
            int r = u >> 3, c4 = (u & 7) << 2;                                       \
            cpa16(ab + (uint32_t)(r * ASTR + c4) * 4u,                               \
                  &g_xr[(size_t)(m0 + r) * DD + kb + c4], (m0 + r) < MTOT);          \
            cpa16(bb + (uint32_t)(r * ASTR + c4) * 4u,                               \
                  &Wt[(size_t)(n0 + r) * DD + kb + c4], true);                       \
        }                                                                            \
    }

    ISSUE_STAGE(0, 0); asm volatile("cp.async.commit_group;");
    ISSUE_STAGE(1, 1); asm volatile("cp.async.commit_group;");

    float acc[4][8][4] = {};

    for (int kc = 0; kc < NKC; kc++) {
        const int stg = kc % 3;
        asm volatile("cp.async.wait_group 1;");
        __syncthreads();

        const uint32_t abase = s32 + stg * STG_BYTES + aoff;
        const uint32_t bbase = s32 + stg * STG_BYTES + boff;
        #pragma unroll
        for (int ks = 0; ks < 4; ks++) {
            const uint32_t k8b = (uint32_t)(ks * 8) * 4u;
            uint32_t af[4][4], bf[8][2];
            #pragma unroll
            for (int mf = 0; mf < 4; mf++)
                ldsm4(af[mf], abase + (uint32_t)(mf * 16 * ASTR) * 4u + k8b);
            #pragma unroll
            for (int p = 0; p < 4; p++)
                ldsm4(&bf[2 * p][0], bbase + (uint32_t)(p * 16 * ASTR) * 4u + k8b);
            #pragma unroll
            for (int mf = 0; mf < 4; mf++)
                #pragma unroll
                for (int nf = 0; nf < 8; nf++)
                    mma_tf32(acc[mf][nf], af[mf], bf[nf]);
        }
        // issue into the slot freed by last iteration (ordered by the sync above)
        if (kc + 2 < NKC) ISSUE_STAGE(kc + 2, (kc + 2) % 3);
        asm volatile("cp.async.commit_group;");
    }

    // epilogue
    #pragma unroll
    for (int mf = 0; mf < 4; mf++) {
        #pragma unroll
        for (int half = 0; half < 2; half++) {
            int m = m0 + wm + mf * 16 + g + half * 8;
            if (m >= MTOT) continue;
            int b = m / SS, s = m - b * SS;
            #pragma unroll
            for (int nf = 0; nf < 8; nf++) {
                int n = n0 + wn + nf * 8 + tg * 2;
                int h = n >> 6, d = n & 63;
                float c0 = acc[mf][nf][half * 2 + 0];
                float c1 = acc[mf][nf][half * 2 + 1];
                if (badd) { c0 += badd[n]; c1 += badd[n + 1]; }
                c0 = __uint_as_float(tf32r(c0 * scl));
                c1 = __uint_as_float(tf32r(c1 * scl));
                if (which == 2) {   // V: transposed [b,h,d,s]
                    float* vp = &g_v[((size_t)(b * HH + h) * HD + d) * VPD + s];
                    vp[0] = c0; vp[VPD] = c1;
                } else {
                    float* op = (which == 0) ? g_q : g_k;
                    *(float2*)&op[((size_t)(b * HH + h) * SS + s) * HD + d] =
                        make_float2(c0, c1);
                }
            }
        }
    }
}

// ---------------- 4) flash attention: all fragments via ldmatrix ----------------
__global__ __launch_bounds__(128) void attn_kernel(float* __restrict__ out)
{
    extern __shared__ float sh[];
    float* ks = sh;                    // [64][KST]  K (key-major)
    float* vs = ks + 64 * KST;         // [64][KST]  V^T (d-major)
    float* ps = vs + 64 * KST;         // [64][KST]  bias tile, then P tile
    const uint32_t s32 = smem_u32(sh);
    const uint32_t ks32 = s32;
    const uint32_t vs32 = s32 + (64 * KST) * 4u;
    const uint32_t ps32 = s32 + (128 * KST) * 4u;

    const int tid = threadIdx.x;
    const int wq = tid >> 5;
    const int lane = tid & 31;
    const int g = lane >> 2, tg = lane & 3;
    const int q0 = blockIdx.x * 64;
    const int bh = blockIdx.y;                 // h*16 + b
    const int h = bh >> 4, b = bh & 15;

    const float* qg = g_q + (size_t)(b * HH + h) * SS * HD;
    const float* kg = g_k + (size_t)(b * HH + h) * SS * HD;
    const float* vg = g_v + (size_t)(b * HH + h) * HD * VPD;   // [d][s]
    const float* biasg = g_bias + (size_t)h * SS * BST;

    const int r0 = q0 + wq * 16 + g;
    const int r1 = r0 + 8;

    // ldmatrix lane address components (B-frag pattern shared by K and V^T)
    const uint32_t fb_row  = (lane & 7) + ((lane >> 4) << 3);
    const uint32_t fb_ksel = (uint32_t)((lane >> 3) & 1) << 2;
    const uint32_t kfoff = ks32 + (fb_row * KST + fb_ksel) * 4u;
    const uint32_t vfoff = vs32 + (fb_row * KST + fb_ksel) * 4u;
    const uint32_t pa_row  = wq * 16 + (lane & 15);
    const uint32_t pa_ksel = (uint32_t)(lane >> 4) << 2;
    const uint32_t pfoff = ps32 + (pa_row * KST + pa_ksel) * 4u;

    // Q fragments — register resident
    uint32_t qf[8][4];
    #pragma unroll
    for (int kk = 0; kk < 8; kk++) {
        int c = kk * 8 + tg;
        qf[kk][0] = (r0 < SS) ? __float_as_uint(qg[(size_t)r0 * HD + c])     : 0u;
        qf[kk][1] = (r1 < SS) ? __float_as_uint(qg[(size_t)r1 * HD + c])     : 0u;
        qf[kk][2] = (r0 < SS) ? __float_as_uint(qg[(size_t)r0 * HD + c + 4]) : 0u;
        qf[kk][3] = (r1 < SS) ? __float_as_uint(qg[(size_t)r1 * HD + c + 4]) : 0u;
    }

    float oacc[8][4];
    #pragma unroll
    for (int nf = 0; nf < 8; nf++)
        #pragma unroll
        for (int r = 0; r < 4; r++) oacc[nf][r] = 0.0f;
    float m0r = -CUDART_INF_F, m1r = -CUDART_INF_F, l0r = 0.0f, l1r = 0.0f;

    #pragma unroll 1
    for (int jt = 0; jt < 10; jt++) {
        const int j0 = jt * 64;
        __syncthreads();
        // stage K (key-major), V^T (d-major, pad rows are zero), bias
        #pragma unroll
        for (int i = 0; i < 8; i++) {
            int u = tid + i * 128;
            int r = u >> 4, c = (u & 15) << 2;
            int srow = j0 + r;
            float4 kv = (srow < SS) ? *(const float4*)&kg[(size_t)srow * HD + c]
                                    : make_float4(0.f, 0.f, 0.f, 0.f);
            *(float4*)&ks[r * KST + c] = kv;
            // V^T: row = d (= r), cols = keys j0+c..; g_v pad (s>=SS) is zero
            *(float4*)&vs[r * KST + c] = *(const float4*)&vg[(size_t)r * VPD + j0 + c];
            int brow = q0 + r; if (brow >= SS) brow = SS - 1;
            float4 bv4 = (j0 + c < SS) ? *(const float4*)&biasg[(size_t)brow * BST + j0 + c]
                                       : make_float4(0.f, 0.f, 0.f, 0.f);
            *(float4*)&ps[r * KST + c] = bv4;
        }
        __syncthreads();

        // S = Q K^T
        float sacc[8][4];
        #pragma unroll
        for (int nf = 0; nf < 8; nf++)
            #pragma unroll
            for (int r = 0; r < 4; r++) sacc[nf][r] = 0.0f;
        #pragma unroll
        for (int kk = 0; kk < 8; kk++) {
            uint32_t bf[8][2];
            #pragma unroll
            for (int p = 0; p < 4; p++)
                ldsm4(&bf[2 * p][0], kfoff + (uint32_t)(p * 16 * KST + kk * 8) * 4u);
            #pragma unroll
            for (int nf = 0; nf < 8; nf++)
                mma_tf32(sacc[nf], qf[kk], bf[nf]);
        }

        // bias add + key mask + row max
        const float* bb0 = &ps[(wq * 16 + g) * KST + 2 * tg];
        const float* bb1 = bb0 + 8 * KST;
        float mx0 = -CUDART_INF_F, mx1 = -CUDART_INF_F;
        #pragma unroll
        for (int nf = 0; nf < 8; nf++) {
            int col = j0 + nf * 8 + 2 * tg;
            float2 b0 = *(const float2*)&bb0[nf * 8];
            float2 b1 = *(const float2*)&bb1[nf * 8];
            sacc[nf][0] += b0.x; sacc[nf][1] += b0.y;
            sacc[nf][2] += b1.x; sacc[nf][3] += b1.y;
            if (col >= SS)     { sacc[nf][0] = -1e30f; sacc[nf][2] = -1e30f; }
            if (col + 1 >= SS) { sacc[nf][1] = -1e30f; sacc[nf][3] = -1e30f; }
            mx0 = fmaxf(mx0, fmaxf(sacc[nf][0], sacc[nf][1]));
            mx1 = fmaxf(mx1, fmaxf(sacc[nf][2], sacc[nf][3]));
        }
        mx0 = fmaxf(mx0, __shfl_xor_sync(0xffffffffu, mx0, 1));
        mx0 = fmaxf(mx0, __shfl_xor_sync(0xffffffffu, mx0, 2));
        mx1 = fmaxf(mx1, __shfl_xor_sync(0xffffffffu, mx1, 1));
        mx1 = fmaxf(mx1, __shfl_xor_sync(0xffffffffu, mx1, 2));

        float mn0 = fmaxf(m0r, mx0), mn1 = fmaxf(m1r, mx1);
        float corr0 = __expf(m0r - mn0), corr1 = __expf(m1r - mn1);
        m0r = mn0; m1r = mn1;

        float rs0 = 0.0f, rs1 = 0.0f;
        float* pw0 = &ps[(wq * 16 + g) * KST + 2 * tg];
        float* pw1 = pw0 + 8 * KST;
        #pragma unroll
        for (int nf = 0; nf < 8; nf++) {
            float p0 = __expf(sacc[nf][0] - mn0);
            float p1 = __expf(sacc[nf][1] - mn0);
            float p2 = __expf(sacc[nf][2] - mn1);
            float p3 = __expf(sacc[nf][3] - mn1);
            rs0 += p0 + p1; rs1 += p2 + p3;
            float2 w0, w1;
            w0.x = __uint_as_float(tf32r(p0)); w0.y = __uint_as_float(tf32r(p1));
            w1.x = __uint_as_float(tf32r(p2)); w1.y = __uint_as_float(tf32r(p3));
            *(float2*)&pw0[nf * 8] = w0;
            *(float2*)&pw1[nf * 8] = w1;
        }
        rs0 += __shfl_xor_sync(0xffffffffu, rs0, 1);
        rs0 += __shfl_xor_sync(0xffffffffu, rs0, 2);
        rs1 += __shfl_xor_sync(0xffffffffu, rs1, 1);
        rs1 += __shfl_xor_sync(0xffffffffu, rs1, 2);
        l0r = l0r * corr0 + rs0;
        l1r = l1r * corr1 + rs1;
        #pragma unroll
        for (int nf = 0; nf < 8; nf++) {
            oacc[nf][0] *= corr0; oacc[nf][1] *= corr0;
            oacc[nf][2] *= corr1; oacc[nf][3] *= corr1;
        }
        __syncwarp();

        // O += P V  (P A-frag + V^T B-frags all via ldmatrix)
        #pragma unroll
        for (int kk = 0; kk < 8; kk++) {
            uint32_t af[4], bf[8][2];
            ldsm4(af, pfoff + (uint32_t)(kk * 8) * 4u);
            #pragma unroll
            for (int p = 0; p < 4; p++)
                ldsm4(&bf[2 * p][0], vfoff + (uint32_t)(p * 16 * KST + kk * 8) * 4u);
            #pragma unroll
            for (int nf = 0; nf < 8; nf++)
                mma_tf32(oacc[nf], af, bf[nf]);
        }
        __syncwarp();
    }

    float inv0 = 1.0f / l0r, inv1 = 1.0f / l1r;
    #pragma unroll
    for (int nf = 0; nf < 8; nf++) {
        int col = h * HD + nf * 8 + 2 * tg;
        if (r0 < SS) {
            float2 v = make_float2(oacc[nf][0] * inv0, oacc[nf][1] * inv0);
            *(float2*)&out[((size_t)b * SS + r0) * DD + col] = v;
        }
        if (r1 < SS) {
            float2 v = make_float2(oacc[nf][2] * inv1, oacc[nf][3] * inv1);
            *(float2*)&out[((size_t)b * SS + r1) * DD + col] = v;
        }
    }
}

// ---------------------------------------------------------------------------
extern "C" void kernel_launch(void* const* d_in, const int* in_sizes, int n_in,
                              void* d_out, int out_size)
{
    const float* X     = (const float*)d_in[0];
    const float* Wq    = (const float*)d_in[1];
    const float* bq    = (const float*)d_in[2];
    const float* Wk    = (const float*)d_in[3];
    const float* Wv    = (const float*)d_in[4];
    const float* bv    = (const float*)d_in[5];
    const float* table = (const float*)d_in[6];
    const int*   idx   = (const int*)d_in[7];
    float* out = (float*)d_out;

    cudaFuncSetAttribute(proj_mma_kernel, cudaFuncAttributeMaxDynamicSharedMemorySize, (int)PROJ_SMEM);
    cudaFuncSetAttribute(attn_kernel, cudaFuncAttributeMaxDynamicSharedMemorySize, (int)ATTN_SMEM);

    bias_kernel<<<(SS * SS + 255) / 256, 256>>>(table, idx);
    xround_kernel<<<(MTOT * DD / 4 + 255) / 256, 256>>>(X);
    transpose_w<<<dim3(DD/32, DD/32, 3), dim3(32, 8)>>>(Wq, Wk, Wv);
    proj_mma_kernel<<<dim3((MTOT + BM - 1) / BM, DD / BN, 3), 128, PROJ_SMEM>>>(bq, bv);
    attn_kernel<<<dim3(10, SB * HH), 128, ATTN_SMEM>>>(out);
}

// round 15
// speedup vs baseline: 1.1629x; 1.1629x over previous
#include <cuda_runtime.h>
#include <math_constants.h>
#include <cstdint>

#define SB 16
#define SS 577
#define DD 768
#define HH 12
#define HD 64
#define MTOT (SB*SS)
#define BST 580          // padded bias row stride

// projection GEMM tiling (round-12 proven config)
#define BM 128
#define BN 128
#define BK 32
#define NKC (DD/BK)      // 24
#define ASTR 36          // padded smem row stride (floats) — bank stride 4
#define STG_FLOATS ((BM+BN)*ASTR)          // 9216
#define STG_BYTES  (STG_FLOATS*4u)         // 36864
#define PROJ_SMEM  (3u*STG_BYTES)          // 110592

// attention tiling: BQ=128, double-buffered K/V
#define KST 68           // K / P / bias smem stride — bank stride 4
#define VST 72           // V smem stride — scalar-LDS conflict-free
#define KS0 0
#define KS1 (64*KST)
#define VS0 (2*64*KST)
#define VS1 (VS0 + 64*VST)
#define PSO (VS0 + 2*64*VST)
#define ATTN_FLOATS (PSO + 128*KST)
#define ATTN_SMEM (ATTN_FLOATS * 4)        // 106496 B

__device__ float g_q[(size_t)SB*HH*SS*HD];
__device__ float g_k[(size_t)SB*HH*SS*HD];
__device__ float g_v[(size_t)SB*HH*SS*HD];
__device__ float g_xr[(size_t)MTOT*DD];
__device__ float g_wt[(size_t)3*DD*DD];
__device__ float g_bias[(size_t)HH*SS*BST];

__device__ __forceinline__ uint32_t tf32r(float x){
    uint32_t o; asm("cvt.rna.tf32.f32 %0, %1;" : "=r"(o) : "f"(x));
    return o;
}
__device__ __forceinline__ uint32_t smem_u32(const void* p){
    uint32_t a;
    asm("{ .reg .u64 t; cvta.to.shared.u64 t, %1; cvt.u32.u64 %0, t; }" : "=r"(a) : "l"(p));
    return a;
}
__device__ __forceinline__ void cpa16(uint32_t dst, const float* src, bool valid){
    int sz = valid ? 16 : 0;
    asm volatile("cp.async.cg.shared.global [%0], [%1], 16, %2;" :: "r"(dst), "l"(src), "r"(sz));
}
__device__ __forceinline__ void ldsm4(uint32_t* r, uint32_t addr){
    asm volatile("ldmatrix.sync.aligned.m8n8.x4.shared.b16 {%0,%1,%2,%3}, [%4];"
        : "=r"(r[0]), "=r"(r[1]), "=r"(r[2]), "=r"(r[3]) : "r"(addr));
}
__device__ __forceinline__ void mma_tf32(float* c, const uint32_t* a, const uint32_t* b){
    asm volatile(
        "mma.sync.aligned.m16n8k8.row.col.f32.tf32.tf32.f32 "
        "{%0,%1,%2,%3}, {%4,%5,%6,%7}, {%8,%9}, {%0,%1,%2,%3};"
        : "+f"(c[0]), "+f"(c[1]), "+f"(c[2]), "+f"(c[3])
        : "r"(a[0]), "r"(a[1]), "r"(a[2]), "r"(a[3]), "r"(b[0]), "r"(b[1]));
}

// ---------------- 1) bias gather (padded rows) ----------------
__global__ __launch_bounds__(256) void bias_kernel(const float* __restrict__ table,
                                                   const int* __restrict__ idx)
{
    int e = blockIdx.x * 256 + threadIdx.x;
    if (e >= SS * SS) return;
    int q = e / SS, k = e - q * SS;
    int i = idx[e];
    #pragma unroll
    for (int h = 0; h < HH; h++)
        g_bias[((size_t)h * SS + q) * BST + k] = table[i * HH + h];
}

// ---------------- 1b) pre-round X to tf32 ----------------
__global__ __launch_bounds__(256) void xround_kernel(const float* __restrict__ X)
{
    size_t i = ((size_t)blockIdx.x * 256 + threadIdx.x) * 4;
    if (i < (size_t)MTOT * DD) {
        float4 v = *(const float4*)&X[i];
        v.x = __uint_as_float(tf32r(v.x)); v.y = __uint_as_float(tf32r(v.y));
        v.z = __uint_as_float(tf32r(v.z)); v.w = __uint_as_float(tf32r(v.w));
        *(float4*)&g_xr[i] = v;
    }
}

// ---------------- 2) weight transpose (+ tf32 round) ----------------
__global__ void transpose_w(const float* __restrict__ Wq,
                            const float* __restrict__ Wk,
                            const float* __restrict__ Wv)
{
    __shared__ float t[32][33];
    int g = blockIdx.z;
    const float* W = (g == 0) ? Wq : (g == 1) ? Wk : Wv;
    int k0 = blockIdx.x * 32, n0 = blockIdx.y * 32;
    int tx = threadIdx.x, ty = threadIdx.y;
    #pragma unroll
    for (int i = 0; i < 32; i += 8)
        t[ty + i][tx] = W[(size_t)(k0 + ty + i) * DD + n0 + tx];
    __syncthreads();
    #pragma unroll
    for (int i = 0; i < 32; i += 8)
        g_wt[(size_t)g * DD * DD + (size_t)(n0 + ty + i) * DD + k0 + tx] =
            __uint_as_float(tf32r(t[tx][ty + i]));
}

// ---------------- 3) projection (round-12 proven): mma.sync + cp.async + ldmatrix ----------------
__global__ __launch_bounds__(256) void proj_mma_kernel(
    const float* __restrict__ bq, const float* __restrict__ bv)
{
    extern __shared__ float smf[];
    const uint32_t s32 = smem_u32(smf);

    const int tid = threadIdx.x;
    const int wid = tid >> 5, lane = tid & 31;
    const int wm = (wid >> 2) * 64;
    const int wn = (wid & 3) * 32;
    const int g = lane >> 2, tg = lane & 3;

    const int m0 = blockIdx.x * BM;
    const int n0 = blockIdx.y * BN;
    const int which = blockIdx.z;
    const float* Wt   = g_wt + (size_t)which * DD * DD;
    float* out        = (which == 0) ? g_q : (which == 1) ? g_k : g_v;
    const float* badd = (which == 0) ? bq : (which == 2) ? bv : nullptr;
    const float scl   = (which == 0) ? 0.125f : 1.0f;

    const uint32_t a_row  = wm + (lane & 15);
    const uint32_t a_ksel = (uint32_t)(lane >> 4) << 2;
    const uint32_t aoff = (a_row * ASTR + a_ksel) * 4u;
    const uint32_t b_row  = wn + (lane & 7) + ((lane >> 4) << 3);
    const uint32_t b_ksel = (uint32_t)((lane >> 3) & 1) << 2;
    const uint32_t boff = (uint32_t)(BM * ASTR) * 4u + (b_row * ASTR + b_ksel) * 4u;

    #define ISSUE_STAGE(kc, stg)                                                     \
    {                                                                                \
        int kb = (kc) * BK;                                                          \
        uint32_t ab = s32 + (stg) * STG_BYTES;                                       \
        uint32_t bb = ab + BM * ASTR * 4u;                                           \
        _Pragma("unroll")                                                            \
        for (int i = 0; i < 4; i++) {                                                \
            int u = tid + i * 256;                                                   \
            int r = u >> 3, c4 = (u & 7) << 2;                                       \
            cpa16(ab + (uint32_t)(r * ASTR + c4) * 4u,                               \
                  &g_xr[(size_t)(m0 + r) * DD + kb + c4], (m0 + r) < MTOT);          \
            cpa16(bb + (uint32_t)(r * ASTR + c4) * 4u,                               \
                  &Wt[(size_t)(n0 + r) * DD + kb + c4], true);                       \
        }                                                                            \
    }

    ISSUE_STAGE(0, 0); asm volatile("cp.async.commit_group;");
    ISSUE_STAGE(1, 1); asm volatile("cp.async.commit_group;");
    ISSUE_STAGE(2, 2); asm volatile("cp.async.commit_group;");

    float acc[4][4][4] = {};

    for (int kc = 0; kc < NKC; kc++) {
        const int stg = kc % 3;
        asm volatile("cp.async.wait_group 2;");
        __syncthreads();

        const uint32_t abase = s32 + stg * STG_BYTES + aoff;
        const uint32_t bbase = s32 + stg * STG_BYTES + boff;
        #pragma unroll
        for (int ks = 0; ks < 4; ks++) {
            const uint32_t k8b = (uint32_t)(ks * 8) * 4u;
            uint32_t af[4][4], bf[4][2];
            #pragma unroll
            for (int mf = 0; mf < 4; mf++)
                ldsm4(af[mf], abase + (uint32_t)(mf * 16 * ASTR) * 4u + k8b);
            #pragma unroll
            for (int p = 0; p < 2; p++)
                ldsm4(&bf[2 * p][0], bbase + (uint32_t)(p * 16 * ASTR) * 4u + k8b);
            #pragma unroll
            for (int mf = 0; mf < 4; mf++)
                #pragma unroll
                for (int nf = 0; nf < 4; nf++)
                    mma_tf32(acc[mf][nf], af[mf], bf[nf]);
        }
        __syncthreads();
        if (kc + 3 < NKC) ISSUE_STAGE(kc + 3, stg);
        asm volatile("cp.async.commit_group;");
    }

    #pragma unroll
    for (int mf = 0; mf < 4; mf++) {
        #pragma unroll
        for (int half = 0; half < 2; half++) {
            int m = m0 + wm + mf * 16 + g + half * 8;
            if (m >= MTOT) continue;
            int b = m / SS, s = m - b * SS;
            #pragma unroll
            for (int nf = 0; nf < 4; nf++) {
                int n = n0 + wn + nf * 8 + tg * 2;
                int h = n >> 6, d = n & 63;
                float c0 = acc[mf][nf][half * 2 + 0];
                float c1 = acc[mf][nf][half * 2 + 1];
                if (badd) { c0 += badd[n]; c1 += badd[n + 1]; }
                float2 v;
                v.x = __uint_as_float(tf32r(c0 * scl));
                v.y = __uint_as_float(tf32r(c1 * scl));
                *(float2*)&out[((size_t)(b * HH + h) * SS + s) * HD + d] = v;
            }
        }
    }
}

// ---------------- 4) attention: BQ=128, 8 warps, double-buffered cp.async K/V ----------------
__global__ __launch_bounds__(256, 2) void attn_kernel(float* __restrict__ out)
{
    extern __shared__ float sh[];
    float* ps = sh + PSO;                  // [128][KST] bias, then P
    const uint32_t s32 = smem_u32(sh);
    const uint32_t ps32 = s32 + PSO * 4u;

    const int tid = threadIdx.x;
    const int wq = tid >> 5;               // 0..7
    const int lane = tid & 31;
    const int g = lane >> 2, tg = lane & 3;
    const int q0 = blockIdx.x * 128;
    const int bh = blockIdx.y;             // h*16 + b
    const int h = bh >> 4, b = bh & 15;

    const float* qg = g_q + (size_t)(b * HH + h) * SS * HD;
    const float* kg = g_k + (size_t)(b * HH + h) * SS * HD;
    const float* vg = g_v + (size_t)(b * HH + h) * SS * HD;
    const float* biasg = g_bias + (size_t)h * SS * BST;

    const int r0 = q0 + wq * 16 + g;
    const int r1 = r0 + 8;

    // fragment lane address components
    const uint32_t fb_row  = (lane & 7) + ((lane >> 4) << 3);
    const uint32_t fb_ksel = (uint32_t)((lane >> 3) & 1) << 2;
    const uint32_t kfrag = (fb_row * KST + fb_ksel) * 4u;
    const uint32_t pa_row  = wq * 16 + (lane & 15);
    const uint32_t pa_ksel = (uint32_t)(lane >> 4) << 2;
    const uint32_t pfoff = ps32 + (pa_row * KST + pa_ksel) * 4u;

    // stage K/V tile jt into buffer bf (cp.async, zero-fill OOB rows)
    #define STAGE_KV(jt, bf)                                                         \
    {                                                                                \
        int jj = (jt) * 64;                                                          \
        uint32_t kdst = s32 + ((bf) ? KS1 : KS0) * 4u;                               \
        uint32_t vdst = s32 + ((bf) ? VS1 : VS0) * 4u;                               \
        _Pragma("unroll")                                                            \
        for (int i = 0; i < 4; i++) {                                                \
            int u = tid + i * 256;                                                   \
            int r = u >> 4, c4 = (u & 15) << 2;                                      \
            bool v = (jj + r) < SS;                                                  \
            cpa16(kdst + (uint32_t)(r * KST + c4) * 4u, &kg[(size_t)(jj + r) * HD + c4], v); \
            cpa16(vdst + (uint32_t)(r * VST + c4) * 4u, &vg[(size_t)(jj + r) * HD + c4], v); \
        }                                                                            \
    }

    // Q fragments — register resident
    uint32_t qf[8][4];
    #pragma unroll
    for (int kk = 0; kk < 8; kk++) {
        int c = kk * 8 + tg;
        qf[kk][0] = (r0 < SS) ? __float_as_uint(qg[(size_t)r0 * HD + c])     : 0u;
        qf[kk][1] = (r1 < SS) ? __float_as_uint(qg[(size_t)r1 * HD + c])     : 0u;
        qf[kk][2] = (r0 < SS) ? __float_as_uint(qg[(size_t)r0 * HD + c + 4]) : 0u;
        qf[kk][3] = (r1 < SS) ? __float_as_uint(qg[(size_t)r1 * HD + c + 4]) : 0u;
    }

    STAGE_KV(0, 0); asm volatile("cp.async.commit_group;");

    float oacc[8][4];
    #pragma unroll
    for (int nf = 0; nf < 8; nf++)
        #pragma unroll
        for (int r = 0; r < 4; r++) oacc[nf][r] = 0.0f;
    float m0r = -CUDART_INF_F, m1r = -CUDART_INF_F, l0r = 0.0f, l1r = 0.0f;

    #pragma unroll 1
    for (int jt = 0; jt < 10; jt++) {
        const int j0 = jt * 64;
        const int buf = jt & 1;
        __syncthreads();   // all reads of previous tile's buffers + P done
        // prefetch next tile into the alternate buffer (just freed)
        if (jt + 1 < 10) STAGE_KV(jt + 1, (jt + 1) & 1);
        asm volatile("cp.async.commit_group;");
        // bias staging for this tile (LDG latency overlaps the wait below + S-MMA)
        #pragma unroll
        for (int i = 0; i < 8; i++) {
            int u = tid + i * 256;
            int r = u >> 4, c = (u & 15) << 2;
            int brow = q0 + r; if (brow >= SS) brow = SS - 1;
            float4 bv4 = (j0 + c < SS) ? *(const float4*)&biasg[(size_t)brow * BST + j0 + c]
                                       : make_float4(0.f, 0.f, 0.f, 0.f);
            *(float4*)&ps[r * KST + c] = bv4;
        }
        asm volatile("cp.async.wait_group 1;");   // current tile's K/V landed
        __syncthreads();                          // K/V + bias visible

        const uint32_t kbase = s32 + (buf ? KS1 : KS0) * 4u + kfrag;
        const float*   vbase = sh + (buf ? VS1 : VS0);

        // S = Q K^T
        float sacc[8][4];
        #pragma unroll
        for (int nf = 0; nf < 8; nf++)
            #pragma unroll
            for (int r = 0; r < 4; r++) sacc[nf][r] = 0.0f;
        #pragma unroll
        for (int kk = 0; kk < 8; kk++) {
            uint32_t bfr[8][2];
            #pragma unroll
            for (int p = 0; p < 4; p++)
                ldsm4(&bfr[2 * p][0], kbase + (uint32_t)(p * 16 * KST + kk * 8) * 4u);
            #pragma unroll
            for (int nf = 0; nf < 8; nf++)
                mma_tf32(sacc[nf], qf[kk], bfr[nf]);
        }

        // bias add + key mask + row max
        const float* bb0 = &ps[(wq * 16 + g) * KST + 2 * tg];
        const float* bb1 = bb0 + 8 * KST;
        float mx0 = -CUDART_INF_F, mx1 = -CUDART_INF_F;
        #pragma unroll
        for (int nf = 0; nf < 8; nf++) {
            int col = j0 + nf * 8 + 2 * tg;
            float2 b0 = *(const float2*)&bb0[nf * 8];
            float2 b1 = *(const float2*)&bb1[nf * 8];
            sacc[nf][0] += b0.x; sacc[nf][1] += b0.y;
            sacc[nf][2] += b1.x; sacc[nf][3] += b1.y;
            if (col >= SS)     { sacc[nf][0] = -1e30f; sacc[nf][2] = -1e30f; }
            if (col + 1 >= SS) { sacc[nf][1] = -1e30f; sacc[nf][3] = -1e30f; }
            mx0 = fmaxf(mx0, fmaxf(sacc[nf][0], sacc[nf][1]));
            mx1 = fmaxf(mx1, fmaxf(sacc[nf][2], sacc[nf][3]));
        }
        mx0 = fmaxf(mx0, __shfl_xor_sync(0xffffffffu, mx0, 1));
        mx0 = fmaxf(mx0, __shfl_xor_sync(0xffffffffu, mx0, 2));
        mx1 = fmaxf(mx1, __shfl_xor_sync(0xffffffffu, mx1, 1));
        mx1 = fmaxf(mx1, __shfl_xor_sync(0xffffffffu, mx1, 2));

        float mn0 = fmaxf(m0r, mx0), mn1 = fmaxf(m1r, mx1);
        float corr0 = __expf(m0r - mn0), corr1 = __expf(m1r - mn1);
        m0r = mn0; m1r = mn1;

        float rs0 = 0.0f, rs1 = 0.0f;
        float* pw0 = &ps[(wq * 16 + g) * KST + 2 * tg];
        float* pw1 = pw0 + 8 * KST;
        #pragma unroll
        for (int nf = 0; nf < 8; nf++) {
            float p0 = __expf(sacc[nf][0] - mn0);
            float p1 = __expf(sacc[nf][1] - mn0);
            float p2 = __expf(sacc[nf][2] - mn1);
            float p3 = __expf(sacc[nf][3] - mn1);
            rs0 += p0 + p1; rs1 += p2 + p3;
            float2 w0, w1;
            w0.x = __uint_as_float(tf32r(p0)); w0.y = __uint_as_float(tf32r(p1));
            w1.x = __uint_as_float(tf32r(p2)); w1.y = __uint_as_float(tf32r(p3));
            *(float2*)&pw0[nf * 8] = w0;
            *(float2*)&pw1[nf * 8] = w1;
        }
        rs0 += __shfl_xor_sync(0xffffffffu, rs0, 1);
        rs0 += __shfl_xor_sync(0xffffffffu, rs0, 2);
        rs1 += __shfl_xor_sync(0xffffffffu, rs1, 1);
        rs1 += __shfl_xor_sync(0xffffffffu, rs1, 2);
        l0r = l0r * corr0 + rs0;
        l1r = l1r * corr1 + rs1;
        #pragma unroll
        for (int nf = 0; nf < 8; nf++) {
            oacc[nf][0] *= corr0; oacc[nf][1] *= corr0;
            oacc[nf][2] *= corr1; oacc[nf][3] *= corr1;
        }
        __syncwarp();

        // O += P V  (P A-frag ldmatrix; V scalar conflict-free)
        #pragma unroll
        for (int kk = 0; kk < 8; kk++) {
            uint32_t af[4];
            ldsm4(af, pfoff + (uint32_t)(kk * 8) * 4u);
            const float* vb0 = &vbase[(kk * 8 + tg) * VST + g];
            const float* vb1 = vb0 + 4 * VST;
            #pragma unroll
            for (int nf = 0; nf < 8; nf++) {
                uint32_t bfv[2];
                bfv[0] = __float_as_uint(vb0[nf * 8]);
                bfv[1] = __float_as_uint(vb1[nf * 8]);
                mma_tf32(oacc[nf], af, bfv);
            }
        }
        __syncwarp();
    }

    float inv0 = 1.0f / l0r, inv1 = 1.0f / l1r;
    #pragma unroll
    for (int nf = 0; nf < 8; nf++) {
        int col = h * HD + nf * 8 + 2 * tg;
        if (r0 < SS) {
            float2 v = make_float2(oacc[nf][0] * inv0, oacc[nf][1] * inv0);
            *(float2*)&out[((size_t)b * SS + r0) * DD + col] = v;
        }
        if (r1 < SS) {
            float2 v = make_float2(oacc[nf][2] * inv1, oacc[nf][3] * inv1);
            *(float2*)&out[((size_t)b * SS + r1) * DD + col] = v;
        }
    }
}

// ---------------------------------------------------------------------------
extern "C" void kernel_launch(void* const* d_in, const int* in_sizes, int n_in,
                              void* d_out, int out_size)
{
    const float* X     = (const float*)d_in[0];
    const float* Wq    = (const float*)d_in[1];
    const float* bq    = (const float*)d_in[2];
    const float* Wk    = (const float*)d_in[3];
    const float* Wv    = (const float*)d_in[4];
    const float* bv    = (const float*)d_in[5];
    const float* table = (const float*)d_in[6];
    const int*   idx   = (const int*)d_in[7];
    float* out = (float*)d_out;

    cudaFuncSetAttribute(proj_mma_kernel, cudaFuncAttributeMaxDynamicSharedMemorySize, (int)PROJ_SMEM);
    cudaFuncSetAttribute(attn_kernel, cudaFuncAttributeMaxDynamicSharedMemorySize, (int)ATTN_SMEM);

    bias_kernel<<<(SS * SS + 255) / 256, 256>>>(table, idx);
    xround_kernel<<<(MTOT * DD / 4 + 255) / 256, 256>>>(X);
    transpose_w<<<dim3(DD/32, DD/32, 3), dim3(32, 8)>>>(Wq, Wk, Wv);
    proj_mma_kernel<<<dim3((MTOT + BM - 1) / BM, DD / BN, 3), 256, PROJ_SMEM>>>(bq, bv);
    attn_kernel<<<dim3(5, SB * HH), 256, ATTN_SMEM>>>(out);
}

// round 16
// speedup vs baseline: 1.8792x; 1.6160x over previous
#include <cuda_runtime.h>
#include <cuda_fp16.h>
#include <math_constants.h>
#include <cstdint>

#define SB 16
#define SS 577
#define DD 768
#define HH 12
#define HD 64
#define MTOT (SB*SS)
#define BST 580          // padded bias row stride (floats)

// projection GEMM tiling (fp16, BK=64)
#define BM 128
#define BN 128
#define BK 64
#define NKC (DD/BK)      // 12
#define ASTRH 72         // smem row stride in halves (144B ≡ 4 banks)
#define STG_BYTES ((BM+BN)*ASTRH*2u)       // 36864
#define PROJ_SMEM (3u*STG_BYTES)           // 110592

// attention smem (bytes): K double-buf, V double-buf, P(half), bias(fp32)
#define KSTH 72          // K/V/P row stride in halves
#define KB0 0
#define KB1 9216
#define VB0 18432
#define VB1 27648
#define PB  36864
#define BB  55296
#define ATTN_SMEM (BB + 128*68*4)          // 90112 B

__device__ __half g_q[(size_t)SB*HH*SS*HD];
__device__ __half g_k[(size_t)SB*HH*SS*HD];
__device__ __half g_v[(size_t)SB*HH*SS*HD];
__device__ __half g_xr[(size_t)MTOT*DD];
__device__ __half g_wt[(size_t)3*DD*DD];
__device__ float  g_bias[(size_t)HH*SS*BST];

__device__ __forceinline__ uint32_t smem_u32(const void* p){
    uint32_t a;
    asm("{ .reg .u64 t; cvta.to.shared.u64 t, %1; cvt.u32.u64 %0, t; }" : "=r"(a) : "l"(p));
    return a;
}
__device__ __forceinline__ void cpa16(uint32_t dst, const void* src, bool valid){
    int sz = valid ? 16 : 0;
    asm volatile("cp.async.cg.shared.global [%0], [%1], 16, %2;" :: "r"(dst), "l"(src), "r"(sz));
}
__device__ __forceinline__ void ldsm4(uint32_t* r, uint32_t addr){
    asm volatile("ldmatrix.sync.aligned.m8n8.x4.shared.b16 {%0,%1,%2,%3}, [%4];"
        : "=r"(r[0]), "=r"(r[1]), "=r"(r[2]), "=r"(r[3]) : "r"(addr));
}
__device__ __forceinline__ void ldsm4t(uint32_t* r, uint32_t addr){
    asm volatile("ldmatrix.sync.aligned.m8n8.x4.trans.shared.b16 {%0,%1,%2,%3}, [%4];"
        : "=r"(r[0]), "=r"(r[1]), "=r"(r[2]), "=r"(r[3]) : "r"(addr));
}
// D(16x8,f32) += A(16x16,f16) * B(16x8,f16)
__device__ __forceinline__ void mma_f16(float* c, const uint32_t* a, const uint32_t* b){
    asm volatile(
        "mma.sync.aligned.m16n8k16.row.col.f32.f16.f16.f32 "
        "{%0,%1,%2,%3}, {%4,%5,%6,%7}, {%8,%9}, {%0,%1,%2,%3};"
        : "+f"(c[0]), "+f"(c[1]), "+f"(c[2]), "+f"(c[3])
        : "r"(a[0]), "r"(a[1]), "r"(a[2]), "r"(a[3]), "r"(b[0]), "r"(b[1]));
}
__device__ __forceinline__ uint32_t h2pack(float a, float b){
    __half2 h = __halves2half2(__float2half_rn(a), __float2half_rn(b));
    return *(uint32_t*)&h;
}

// ---------------- 1) bias gather (padded rows) ----------------
__global__ __launch_bounds__(256) void bias_kernel(const float* __restrict__ table,
                                                   const int* __restrict__ idx)
{
    int e = blockIdx.x * 256 + threadIdx.x;
    if (e >= SS * SS) return;
    int q = e / SS, k = e - q * SS;
    int i = idx[e];
    #pragma unroll
    for (int h = 0; h < HH; h++)
        g_bias[((size_t)h * SS + q) * BST + k] = table[i * HH + h];
}

// ---------------- 1b) X -> fp16 ----------------
__global__ __launch_bounds__(256) void xhalf_kernel(const float* __restrict__ X)
{
    size_t i = ((size_t)blockIdx.x * 256 + threadIdx.x) * 4;
    if (i < (size_t)MTOT * DD) {
        float4 v = *(const float4*)&X[i];
        uint2 o;
        o.x = h2pack(v.x, v.y);
        o.y = h2pack(v.z, v.w);
        *(uint2*)&g_xr[i] = o;
    }
}

// ---------------- 2) weight transpose -> fp16 ----------------
__global__ void transpose_w(const float* __restrict__ Wq,
                            const float* __restrict__ Wk,
                            const float* __restrict__ Wv)
{
    __shared__ float t[32][33];
    int g = blockIdx.z;
    const float* W = (g == 0) ? Wq : (g == 1) ? Wk : Wv;
    int k0 = blockIdx.x * 32, n0 = blockIdx.y * 32;
    int tx = threadIdx.x, ty = threadIdx.y;
    #pragma unroll
    for (int i = 0; i < 32; i += 8)
        t[ty + i][tx] = W[(size_t)(k0 + ty + i) * DD + n0 + tx];
    __syncthreads();
    #pragma unroll
    for (int i = 0; i < 32; i += 8)
        g_wt[(size_t)g * DD * DD + (size_t)(n0 + ty + i) * DD + k0 + tx] =
            __float2half_rn(t[tx][ty + i]);
}

// ---------------- 3) projection: fp16 mma.sync m16n8k16 + cp.async + ldmatrix ----------------
__global__ __launch_bounds__(256) void proj_mma_kernel(
    const float* __restrict__ bq, const float* __restrict__ bv)
{
    extern __shared__ char smc[];
    const uint32_t s32 = smem_u32(smc);

    const int tid = threadIdx.x;
    const int wid = tid >> 5, lane = tid & 31;
    const int wm = (wid >> 2) * 64;
    const int wn = (wid & 3) * 32;
    const int g = lane >> 2, tg = lane & 3;

    const int m0 = blockIdx.x * BM;
    const int n0 = blockIdx.y * BN;
    const int which = blockIdx.z;
    const __half* Wt  = g_wt + (size_t)which * DD * DD;
    __half* out       = (which == 0) ? g_q : (which == 1) ? g_k : g_v;
    const float* badd = (which == 0) ? bq : (which == 2) ? bv : nullptr;
    const float scl   = (which == 0) ? 0.125f : 1.0f;

    // ldmatrix lane address components (byte offsets; halves*2)
    const uint32_t a_row  = wm + (lane & 15);
    const uint32_t a_ksel = (uint32_t)(lane >> 4) << 3;            // 0 or 8 halves
    const uint32_t aoff = (a_row * ASTRH + a_ksel) * 2u;
    const uint32_t b_row  = wn + (lane & 7) + ((lane >> 4) << 3);
    const uint32_t b_ksel = (uint32_t)((lane >> 3) & 1) << 3;
    const uint32_t boff = (uint32_t)(BM * ASTRH) * 2u + (b_row * ASTRH + b_ksel) * 2u;

    #define ISSUE_STAGE(kc, stg)                                                     \
    {                                                                                \
        int kb = (kc) * BK;                                                          \
        uint32_t ab = s32 + (stg) * STG_BYTES;                                       \
        uint32_t bb = ab + BM * ASTRH * 2u;                                          \
        _Pragma("unroll")                                                            \
        for (int i = 0; i < 4; i++) {                                                \
            int u = tid + i * 256;                                                   \
            int r = u >> 3, c8 = (u & 7) << 3;                                       \
            cpa16(ab + (uint32_t)(r * ASTRH + c8) * 2u,                              \
                  &g_xr[(size_t)(m0 + r) * DD + kb + c8], (m0 + r) < MTOT);          \
            cpa16(bb + (uint32_t)(r * ASTRH + c8) * 2u,                              \
                  &Wt[(size_t)(n0 + r) * DD + kb + c8], true);                       \
        }                                                                            \
    }

    ISSUE_STAGE(0, 0); asm volatile("cp.async.commit_group;");
    ISSUE_STAGE(1, 1); asm volatile("cp.async.commit_group;");
    ISSUE_STAGE(2, 2); asm volatile("cp.async.commit_group;");

    float acc[4][4][4] = {};

    for (int kc = 0; kc < NKC; kc++) {
        const int stg = kc % 3;
        asm volatile("cp.async.wait_group 2;");
        __syncthreads();

        const uint32_t abase = s32 + stg * STG_BYTES + aoff;
        const uint32_t bbase = s32 + stg * STG_BYTES + boff;
        #pragma unroll
        for (int ks = 0; ks < 4; ks++) {
            const uint32_t kb2 = (uint32_t)(ks * 16) * 2u;   // 16 halves per kstep
            uint32_t af[4][4], bf[4][2];
            #pragma unroll
            for (int mf = 0; mf < 4; mf++)
                ldsm4(af[mf], abase + (uint32_t)(mf * 16 * ASTRH) * 2u + kb2);
            #pragma unroll
            for (int p = 0; p < 2; p++)
                ldsm4(&bf[2 * p][0], bbase + (uint32_t)(p * 16 * ASTRH) * 2u + kb2);
            #pragma unroll
            for (int mf = 0; mf < 4; mf++)
                #pragma unroll
                for (int nf = 0; nf < 4; nf++)
                    mma_f16(acc[mf][nf], af[mf], bf[nf]);
        }
        __syncthreads();
        if (kc + 3 < NKC) ISSUE_STAGE(kc + 3, stg);
        asm volatile("cp.async.commit_group;");
    }

    // epilogue: fp32 acc + bias, scale, store half2 into [b,h,s,64]
    #pragma unroll
    for (int mf = 0; mf < 4; mf++) {
        #pragma unroll
        for (int half = 0; half < 2; half++) {
            int m = m0 + wm + mf * 16 + g + half * 8;
            if (m >= MTOT) continue;
            int b = m / SS, s = m - b * SS;
            #pragma unroll
            for (int nf = 0; nf < 4; nf++) {
                int n = n0 + wn + nf * 8 + tg * 2;
                int h = n >> 6, d = n & 63;
                float c0 = acc[mf][nf][half * 2 + 0];
                float c1 = acc[mf][nf][half * 2 + 1];
                if (badd) { c0 += badd[n]; c1 += badd[n + 1]; }
                uint32_t hv = h2pack(c0 * scl, c1 * scl);
                *(uint32_t*)&out[((size_t)(b * HH + h) * SS + s) * HD + d] = hv;
            }
        }
    }
}

// ---------------- 4) attention: fp16 mma m16n8k16, BQ=128, double-buffered K/V ----------------
__global__ __launch_bounds__(256, 2) void attn_kernel(float* __restrict__ out)
{
    extern __shared__ char sh[];
    const uint32_t s32 = smem_u32(sh);
    __half* pp  = (__half*)(sh + PB);      // [128][KSTH] P (half)
    float*  bsm = (float*)(sh + BB);       // [128][68]   bias (fp32)

    const int tid = threadIdx.x;
    const int wq = tid >> 5;               // 0..7
    const int lane = tid & 31;
    const int g = lane >> 2, tg = lane & 3;
    const int q0 = blockIdx.x * 128;
    const int bh = blockIdx.y;             // h*16 + b
    const int h = bh >> 4, b = bh & 15;

    const __half* qg = g_q + (size_t)(b * HH + h) * SS * HD;
    const __half* kg = g_k + (size_t)(b * HH + h) * SS * HD;
    const __half* vg = g_v + (size_t)(b * HH + h) * SS * HD;
    const float* biasg = g_bias + (size_t)h * SS * BST;

    const int r0 = q0 + wq * 16 + g;
    const int r1 = r0 + 8;

    // fragment lane address components (byte offsets)
    const uint32_t kb_row  = (lane & 7) + ((lane >> 4) << 3);        // K B-frag
    const uint32_t kb_ksel = (uint32_t)((lane >> 3) & 1) << 3;
    const uint32_t kfrag = (kb_row * KSTH + kb_ksel) * 2u;
    const uint32_t v_row  = (lane & 7) + (((lane >> 3) & 1) << 3);   // V trans-frag (keys)
    const uint32_t v_dsel = (uint32_t)(lane >> 4) << 3;              // d-base 0/8
    const uint32_t vfrag = (v_row * KSTH + v_dsel) * 2u;
    const uint32_t pa_row = wq * 16 + (lane & 15);                   // P A-frag
    const uint32_t pa_ksel = (uint32_t)(lane >> 4) << 3;
    const uint32_t pfoff = s32 + PB + (pa_row * KSTH + pa_ksel) * 2u;

    #define STAGE_KV(jt, bf)                                                         \
    {                                                                                \
        int jj = (jt) * 64;                                                          \
        uint32_t kdst = s32 + ((bf) ? KB1 : KB0);                                    \
        uint32_t vdst = s32 + ((bf) ? VB1 : VB0);                                    \
        _Pragma("unroll")                                                            \
        for (int i = 0; i < 2; i++) {                                                \
            int u = tid + i * 256;                                                   \
            int r = u >> 3, c8 = (u & 7) << 3;                                       \
            bool v = (jj + r) < SS;                                                  \
            cpa16(kdst + (uint32_t)(r * KSTH + c8) * 2u, &kg[(size_t)(jj + r) * HD + c8], v); \
            cpa16(vdst + (uint32_t)(r * KSTH + c8) * 2u, &vg[(size_t)(jj + r) * HD + c8], v); \
        }                                                                            \
    }

    // Q fragments — register resident (4 ksteps x 4 regs)
    uint32_t qf[4][4];
    #pragma unroll
    for (int kk = 0; kk < 4; kk++) {
        int c = kk * 16 + 2 * tg;
        qf[kk][0] = (r0 < SS) ? *(const uint32_t*)&qg[(size_t)r0 * HD + c]     : 0u;
        qf[kk][1] = (r1 < SS) ? *(const uint32_t*)&qg[(size_t)r1 * HD + c]     : 0u;
        qf[kk][2] = (r0 < SS) ? *(const uint32_t*)&qg[(size_t)r0 * HD + c + 8] : 0u;
        qf[kk][3] = (r1 < SS) ? *(const uint32_t*)&qg[(size_t)r1 * HD + c + 8] : 0u;
    }

    STAGE_KV(0, 0); asm volatile("cp.async.commit_group;");

    float oacc[8][4];
    #pragma unroll
    for (int nf = 0; nf < 8; nf++)
        #pragma unroll
        for (int r = 0; r < 4; r++) oacc[nf][r] = 0.0f;
    float m0r = -CUDART_INF_F, m1r = -CUDART_INF_F, l0r = 0.0f, l1r = 0.0f;

    #pragma unroll 1
    for (int jt = 0; jt < 10; jt++) {
        const int j0 = jt * 64;
        const int buf = jt & 1;
        __syncthreads();
        if (jt + 1 < 10) STAGE_KV(jt + 1, (jt + 1) & 1);
        asm volatile("cp.async.commit_group;");
        // bias tile staging (fp32)
        #pragma unroll
        for (int i = 0; i < 8; i++) {
            int u = tid + i * 256;
            int r = u >> 4, c = (u & 15) << 2;
            int brow = q0 + r; if (brow >= SS) brow = SS - 1;
            float4 bv4 = (j0 + c < SS) ? *(const float4*)&biasg[(size_t)brow * BST + j0 + c]
                                       : make_float4(0.f, 0.f, 0.f, 0.f);
            *(float4*)&bsm[r * 68 + c] = bv4;
        }
        asm volatile("cp.async.wait_group 1;");
        __syncthreads();

        const uint32_t kbase = s32 + (buf ? KB1 : KB0) + kfrag;
        const uint32_t vbase = s32 + (buf ? VB1 : VB0) + vfrag;

        // S = Q K^T  (4 ksteps of 16 d)
        float sacc[8][4];
        #pragma unroll
        for (int nf = 0; nf < 8; nf++)
            #pragma unroll
            for (int r = 0; r < 4; r++) sacc[nf][r] = 0.0f;
        #pragma unroll
        for (int kk = 0; kk < 4; kk++) {
            uint32_t bfr[8][2];
            #pragma unroll
            for (int p = 0; p < 4; p++)
                ldsm4(&bfr[2 * p][0], kbase + (uint32_t)(p * 16 * KSTH) * 2u + kk * 32u);
            #pragma unroll
            for (int nf = 0; nf < 8; nf++)
                mma_f16(sacc[nf], qf[kk], bfr[nf]);
        }

        // bias add + key mask + row max
        const float* bb0 = &bsm[(wq * 16 + g) * 68 + 2 * tg];
        const float* bb1 = bb0 + 8 * 68;
        float mx0 = -CUDART_INF_F, mx1 = -CUDART_INF_F;
        #pragma unroll
        for (int nf = 0; nf < 8; nf++) {
            int col = j0 + nf * 8 + 2 * tg;
            float2 b0 = *(const float2*)&bb0[nf * 8];
            float2 b1 = *(const float2*)&bb1[nf * 8];
            sacc[nf][0] += b0.x; sacc[nf][1] += b0.y;
            sacc[nf][2] += b1.x; sacc[nf][3] += b1.y;
            if (col >= SS)     { sacc[nf][0] = -1e30f; sacc[nf][2] = -1e30f; }
            if (col + 1 >= SS) { sacc[nf][1] = -1e30f; sacc[nf][3] = -1e30f; }
            mx0 = fmaxf(mx0, fmaxf(sacc[nf][0], sacc[nf][1]));
            mx1 = fmaxf(mx1, fmaxf(sacc[nf][2], sacc[nf][3]));
        }
        mx0 = fmaxf(mx0, __shfl_xor_sync(0xffffffffu, mx0, 1));
        mx0 = fmaxf(mx0, __shfl_xor_sync(0xffffffffu, mx0, 2));
        mx1 = fmaxf(mx1, __shfl_xor_sync(0xffffffffu, mx1, 1));
        mx1 = fmaxf(mx1, __shfl_xor_sync(0xffffffffu, mx1, 2));

        float mn0 = fmaxf(m0r, mx0), mn1 = fmaxf(m1r, mx1);
        float corr0 = __expf(m0r - mn0), corr1 = __expf(m1r - mn1);
        m0r = mn0; m1r = mn1;

        float rs0 = 0.0f, rs1 = 0.0f;
        __half* pw0 = pp + (wq * 16 + g) * KSTH + 2 * tg;
        __half* pw1 = pw0 + 8 * KSTH;
        #pragma unroll
        for (int nf = 0; nf < 8; nf++) {
            float p0 = __expf(sacc[nf][0] - mn0);
            float p1 = __expf(sacc[nf][1] - mn0);
            float p2 = __expf(sacc[nf][2] - mn1);
            float p3 = __expf(sacc[nf][3] - mn1);
            rs0 += p0 + p1; rs1 += p2 + p3;
            *(uint32_t*)&pw0[nf * 8] = h2pack(p0, p1);
            *(uint32_t*)&pw1[nf * 8] = h2pack(p2, p3);
        }
        rs0 += __shfl_xor_sync(0xffffffffu, rs0, 1);
        rs0 += __shfl_xor_sync(0xffffffffu, rs0, 2);
        rs1 += __shfl_xor_sync(0xffffffffu, rs1, 1);
        rs1 += __shfl_xor_sync(0xffffffffu, rs1, 2);
        l0r = l0r * corr0 + rs0;
        l1r = l1r * corr1 + rs1;
        #pragma unroll
        for (int nf = 0; nf < 8; nf++) {
            oacc[nf][0] *= corr0; oacc[nf][1] *= corr0;
            oacc[nf][2] *= corr1; oacc[nf][3] *= corr1;
        }
        __syncwarp();

        // O += P V  (P A-frag ldmatrix; V B-frags ldmatrix.trans; 4 ksteps of 16 keys)
        #pragma unroll
        for (int kk = 0; kk < 4; kk++) {
            uint32_t af[4], bfv[8][2];
            ldsm4(af, pfoff + kk * 32u);
            #pragma unroll
            for (int p = 0; p < 4; p++)
                ldsm4t(&bfv[2 * p][0],
                       vbase + (uint32_t)(kk * 16 * KSTH) * 2u + p * 32u);
            #pragma unroll
            for (int nf = 0; nf < 8; nf++)
                mma_f16(oacc[nf], af, bfv[nf]);
        }
        __syncwarp();
    }

    float inv0 = 1.0f / l0r, inv1 = 1.0f / l1r;
    #pragma unroll
    for (int nf = 0; nf < 8; nf++) {
        int col = h * HD + nf * 8 + 2 * tg;
        if (r0 < SS) {
            float2 v = make_float2(oacc[nf][0] * inv0, oacc[nf][1] * inv0);
            *(float2*)&out[((size_t)b * SS + r0) * DD + col] = v;
        }
        if (r1 < SS) {
            float2 v = make_float2(oacc[nf][2] * inv1, oacc[nf][3] * inv1);
            *(float2*)&out[((size_t)b * SS + r1) * DD + col] = v;
        }
    }
}

// ---------------------------------------------------------------------------
extern "C" void kernel_launch(void* const* d_in, const int* in_sizes, int n_in,
                              void* d_out, int out_size)
{
    const float* X     = (const float*)d_in[0];
    const float* Wq    = (const float*)d_in[1];
    const float* bq    = (const float*)d_in[2];
    const float* Wk    = (const float*)d_in[3];
    const float* Wv    = (const float*)d_in[4];
    const float* bv    = (const float*)d_in[5];
    const float* table = (const float*)d_in[6];
    const int*   idx   = (const int*)d_in[7];
    float* out = (float*)d_out;

    cudaFuncSetAttribute(proj_mma_kernel, cudaFuncAttributeMaxDynamicSharedMemorySize, (int)PROJ_SMEM);
    cudaFuncSetAttribute(attn_kernel, cudaFuncAttributeMaxDynamicSharedMemorySize, (int)ATTN_SMEM);

    bias_kernel<<<(SS * SS + 255) / 256, 256>>>(table, idx);
    xhalf_kernel<<<(MTOT * DD / 4 + 255) / 256, 256>>>(X);
    transpose_w<<<dim3(DD/32, DD/32, 3), dim3(32, 8)>>>(Wq, Wk, Wv);
    proj_mma_kernel<<<dim3((MTOT + BM - 1) / BM, DD / BN, 3), 256, PROJ_SMEM>>>(bq, bv);
    attn_kernel<<<dim3(5, SB * HH), 256, ATTN_SMEM>>>(out);
}

// round 17
// speedup vs baseline: 2.1004x; 1.1177x over previous
#include <cuda_runtime.h>
#include <cuda_fp16.h>
#include <math_constants.h>
#include <cstdint>

#define SB 16
#define SS 577
#define DD 768
#define HH 12
#define HD 64
#define MTOT (SB*SS)
#define BSTH 584         // padded bias row stride (halves; 1168B rows, 16B-aligned)

// projection GEMM tiling (fp16, BK=64)
#define BM 128
#define BN 128
#define BK 64
#define NKC (DD/BK)      // 12
#define ASTRH 72         // smem row stride in halves (144B ≡ 4 banks)
#define STG_BYTES ((BM+BN)*ASTRH*2u)       // 36864
#define PROJ_SMEM (3u*STG_BYTES)           // 110592

// attention smem (bytes): K x2, V x2, P, bias(fp16) x2
#define KSTH 72
#define KB0 0
#define KB1 9216
#define VB0 18432
#define VB1 27648
#define PB  36864
#define BB0 55296
#define BB1 73728
#define ATTN_SMEM (BB1 + 18432)            // 92160 B -> 2 blocks/SM

__device__ __half g_q[(size_t)SB*HH*SS*HD];
__device__ __half g_k[(size_t)SB*HH*SS*HD];
__device__ __half g_v[(size_t)SB*HH*SS*HD];
__device__ __half g_xr[(size_t)MTOT*DD];
__device__ __half g_wt[(size_t)3*DD*DD];
__device__ __half g_biasH[(size_t)HH*SS*BSTH];

__device__ __forceinline__ uint32_t smem_u32(const void* p){
    uint32_t a;
    asm("{ .reg .u64 t; cvta.to.shared.u64 t, %1; cvt.u32.u64 %0, t; }" : "=r"(a) : "l"(p));
    return a;
}
__device__ __forceinline__ void cpa16(uint32_t dst, const void* src, bool valid){
    int sz = valid ? 16 : 0;
    asm volatile("cp.async.cg.shared.global [%0], [%1], 16, %2;" :: "r"(dst), "l"(src), "r"(sz));
}
__device__ __forceinline__ void ldsm4(uint32_t* r, uint32_t addr){
    asm volatile("ldmatrix.sync.aligned.m8n8.x4.shared.b16 {%0,%1,%2,%3}, [%4];"
        : "=r"(r[0]), "=r"(r[1]), "=r"(r[2]), "=r"(r[3]) : "r"(addr));
}
__device__ __forceinline__ void ldsm4t(uint32_t* r, uint32_t addr){
    asm volatile("ldmatrix.sync.aligned.m8n8.x4.trans.shared.b16 {%0,%1,%2,%3}, [%4];"
        : "=r"(r[0]), "=r"(r[1]), "=r"(r[2]), "=r"(r[3]) : "r"(addr));
}
__device__ __forceinline__ void mma_f16(float* c, const uint32_t* a, const uint32_t* b){
    asm volatile(
        "mma.sync.aligned.m16n8k16.row.col.f32.f16.f16.f32 "
        "{%0,%1,%2,%3}, {%4,%5,%6,%7}, {%8,%9}, {%0,%1,%2,%3};"
        : "+f"(c[0]), "+f"(c[1]), "+f"(c[2]), "+f"(c[3])
        : "r"(a[0]), "r"(a[1]), "r"(a[2]), "r"(a[3]), "r"(b[0]), "r"(b[1]));
}
__device__ __forceinline__ uint32_t h2pack(float a, float b){
    __half2 h = __halves2half2(__float2half_rn(a), __float2half_rn(b));
    return *(uint32_t*)&h;
}

// ---------------- 1) bias gather -> fp16 (padded rows) ----------------
__global__ __launch_bounds__(256) void bias_kernel(const float* __restrict__ table,
                                                   const int* __restrict__ idx)
{
    int e = blockIdx.x * 256 + threadIdx.x;
    if (e >= SS * SS) return;
    int q = e / SS, k = e - q * SS;
    int i = idx[e];
    #pragma unroll
    for (int h = 0; h < HH; h++)
        g_biasH[((size_t)h * SS + q) * BSTH + k] = __float2half_rn(table[i * HH + h]);
}

// ---------------- 1b) X -> fp16 ----------------
__global__ __launch_bounds__(256) void xhalf_kernel(const float* __restrict__ X)
{
    size_t i = ((size_t)blockIdx.x * 256 + threadIdx.x) * 4;
    if (i < (size_t)MTOT * DD) {
        float4 v = *(const float4*)&X[i];
        uint2 o;
        o.x = h2pack(v.x, v.y);
        o.y = h2pack(v.z, v.w);
        *(uint2*)&g_xr[i] = o;
    }
}

// ---------------- 2) weight transpose -> fp16 ----------------
__global__ void transpose_w(const float* __restrict__ Wq,
                            const float* __restrict__ Wk,
                            const float* __restrict__ Wv)
{
    __shared__ float t[32][33];
    int g = blockIdx.z;
    const float* W = (g == 0) ? Wq : (g == 1) ? Wk : Wv;
    int k0 = blockIdx.x * 32, n0 = blockIdx.y * 32;
    int tx = threadIdx.x, ty = threadIdx.y;
    #pragma unroll
    for (int i = 0; i < 32; i += 8)
        t[ty + i][tx] = W[(size_t)(k0 + ty + i) * DD + n0 + tx];
    __syncthreads();
    #pragma unroll
    for (int i = 0; i < 32; i += 8)
        g_wt[(size_t)g * DD * DD + (size_t)(n0 + ty + i) * DD + k0 + tx] =
            __float2half_rn(t[tx][ty + i]);
}

// ---------------- 3) projection: fp16 m16n8k16, one sync per chunk ----------------
__global__ __launch_bounds__(256) void proj_mma_kernel(
    const float* __restrict__ bq, const float* __restrict__ bv)
{
    extern __shared__ char smc[];
    const uint32_t s32 = smem_u32(smc);

    const int tid = threadIdx.x;
    const int wid = tid >> 5, lane = tid & 31;
    const int wm = (wid >> 2) * 64;
    const int wn = (wid & 3) * 32;
    const int g = lane >> 2, tg = lane & 3;

    const int m0 = blockIdx.x * BM;
    const int n0 = blockIdx.y * BN;
    const int which = blockIdx.z;
    const __half* Wt  = g_wt + (size_t)which * DD * DD;
    __half* out       = (which == 0) ? g_q : (which == 1) ? g_k : g_v;
    const float* badd = (which == 0) ? bq : (which == 2) ? bv : nullptr;
    const float scl   = (which == 0) ? 0.125f : 1.0f;

    const uint32_t a_row  = wm + (lane & 15);
    const uint32_t a_ksel = (uint32_t)(lane >> 4) << 3;
    const uint32_t aoff = (a_row * ASTRH + a_ksel) * 2u;
    const uint32_t b_row  = wn + (lane & 7) + ((lane >> 4) << 3);
    const uint32_t b_ksel = (uint32_t)((lane >> 3) & 1) << 3;
    const uint32_t boff = (uint32_t)(BM * ASTRH) * 2u + (b_row * ASTRH + b_ksel) * 2u;

    #define ISSUE_STAGE(kc, stg)                                                     \
    {                                                                                \
        int kb = (kc) * BK;                                                          \
        uint32_t ab = s32 + (stg) * STG_BYTES;                                       \
        uint32_t bb = ab + BM * ASTRH * 2u;                                          \
        _Pragma("unroll")                                                            \
        for (int i = 0; i < 4; i++) {                                                \
            int u = tid + i * 256;                                                   \
            int r = u >> 3, c8 = (u & 7) << 3;                                       \
            cpa16(ab + (uint32_t)(r * ASTRH + c8) * 2u,                              \
                  &g_xr[(size_t)(m0 + r) * DD + kb + c8], (m0 + r) < MTOT);          \
            cpa16(bb + (uint32_t)(r * ASTRH + c8) * 2u,                              \
                  &Wt[(size_t)(n0 + r) * DD + kb + c8], true);                       \
        }                                                                            \
    }

    ISSUE_STAGE(0, 0); asm volatile("cp.async.commit_group;");
    ISSUE_STAGE(1, 1); asm volatile("cp.async.commit_group;");

    float acc[4][4][4] = {};

    for (int kc = 0; kc < NKC; kc++) {
        const int stg = kc % 3;
        asm volatile("cp.async.wait_group 1;");   // chunk kc landed (kc+1 in flight)
        __syncthreads();                          // visibility + frees stage (kc+2)%3
        if (kc + 2 < NKC) ISSUE_STAGE(kc + 2, (kc + 2) % 3);
        asm volatile("cp.async.commit_group;");

        const uint32_t abase = s32 + stg * STG_BYTES + aoff;
        const uint32_t bbase = s32 + stg * STG_BYTES + boff;
        #pragma unroll
        for (int ks = 0; ks < 4; ks++) {
            const uint32_t kb2 = (uint32_t)(ks * 16) * 2u;
            uint32_t af[4][4], bf[4][2];
            #pragma unroll
            for (int mf = 0; mf < 4; mf++)
                ldsm4(af[mf], abase + (uint32_t)(mf * 16 * ASTRH) * 2u + kb2);
            #pragma unroll
            for (int p = 0; p < 2; p++)
                ldsm4(&bf[2 * p][0], bbase + (uint32_t)(p * 16 * ASTRH) * 2u + kb2);
            #pragma unroll
            for (int mf = 0; mf < 4; mf++)
                #pragma unroll
                for (int nf = 0; nf < 4; nf++)
                    mma_f16(acc[mf][nf], af[mf], bf[nf]);
        }
    }

    // epilogue: fp32 acc + bias, scale, store half2 into [b,h,s,64]
    #pragma unroll
    for (int mf = 0; mf < 4; mf++) {
        #pragma unroll
        for (int half = 0; half < 2; half++) {
            int m = m0 + wm + mf * 16 + g + half * 8;
            if (m >= MTOT) continue;
            int b = m / SS, s = m - b * SS;
            #pragma unroll
            for (int nf = 0; nf < 4; nf++) {
                int n = n0 + wn + nf * 8 + tg * 2;
                int h = n >> 6, d = n & 63;
                float c0 = acc[mf][nf][half * 2 + 0];
                float c1 = acc[mf][nf][half * 2 + 1];
                if (badd) { c0 += badd[n]; c1 += badd[n + 1]; }
                uint32_t hv = h2pack(c0 * scl, c1 * scl);
                *(uint32_t*)&out[((size_t)(b * HH + h) * SS + s) * HD + d] = hv;
            }
        }
    }
}

// ---------------- 4) attention: fp16 mma, cp.async K/V + fp16 bias prefetch ----------------
__global__ __launch_bounds__(256, 2) void attn_kernel(float* __restrict__ out)
{
    extern __shared__ char sh[];
    const uint32_t s32 = smem_u32(sh);
    __half* pp  = (__half*)(sh + PB);      // [128][KSTH] P (half)

    const int tid = threadIdx.x;
    const int wq = tid >> 5;
    const int lane = tid & 31;
    const int g = lane >> 2, tg = lane & 3;
    const int q0 = blockIdx.x * 128;
    const int bh = blockIdx.y;             // h*16 + b
    const int h = bh >> 4, b = bh & 15;

    const __half* qg = g_q + (size_t)(b * HH + h) * SS * HD;
    const __half* kg = g_k + (size_t)(b * HH + h) * SS * HD;
    const __half* vg = g_v + (size_t)(b * HH + h) * SS * HD;
    const __half* biasg = g_biasH + (size_t)h * SS * BSTH;

    const int r0 = q0 + wq * 16 + g;
    const int r1 = r0 + 8;

    const uint32_t kb_row  = (lane & 7) + ((lane >> 4) << 3);
    const uint32_t kb_ksel = (uint32_t)((lane >> 3) & 1) << 3;
    const uint32_t kfrag = (kb_row * KSTH + kb_ksel) * 2u;
    const uint32_t v_row  = (lane & 7) + (((lane >> 3) & 1) << 3);
    const uint32_t v_dsel = (uint32_t)(lane >> 4) << 3;
    const uint32_t vfrag = (v_row * KSTH + v_dsel) * 2u;
    const uint32_t pa_row = wq * 16 + (lane & 15);
    const uint32_t pa_ksel = (uint32_t)(lane >> 4) << 3;
    const uint32_t pfoff = s32 + PB + (pa_row * KSTH + pa_ksel) * 2u;

    #define STAGE_KV(jt, bf)                                                         \
    {                                                                                \
        int jj = (jt) * 64;                                                          \
        uint32_t kdst = s32 + ((bf) ? KB1 : KB0);                                    \
        uint32_t vdst = s32 + ((bf) ? VB1 : VB0);                                    \
        _Pragma("unroll")                                                            \
        for (int i = 0; i < 2; i++) {                                                \
            int u = tid + i * 256;                                                   \
            int r = u >> 3, c8 = (u & 7) << 3;                                       \
            bool v = (jj + r) < SS;                                                  \
            cpa16(kdst + (uint32_t)(r * KSTH + c8) * 2u, &kg[(size_t)(jj + r) * HD + c8], v); \
            cpa16(vdst + (uint32_t)(r * KSTH + c8) * 2u, &vg[(size_t)(jj + r) * HD + c8], v); \
        }                                                                            \
    }
    // bias tile: rows = q (128), cols = 64 keys (fp16)
    #define STAGE_BIAS(jt, bf)                                                       \
    {                                                                                \
        int jj = (jt) * 64;                                                          \
        uint32_t bdst = s32 + ((bf) ? BB1 : BB0);                                    \
        _Pragma("unroll")                                                            \
        for (int i = 0; i < 4; i++) {                                                \
            int u = tid + i * 256;                                                   \
            int r = u >> 3, c8 = (u & 7) << 3;                                       \
            int brow = q0 + r; if (brow >= SS) brow = SS - 1;                        \
            cpa16(bdst + (uint32_t)(r * KSTH + c8) * 2u,                             \
                  &biasg[(size_t)brow * BSTH + jj + c8], (jj + c8) < SS);            \
        }                                                                            \
    }

    // Q fragments — register resident
    uint32_t qf[4][4];
    #pragma unroll
    for (int kk = 0; kk < 4; kk++) {
        int c = kk * 16 + 2 * tg;
        qf[kk][0] = (r0 < SS) ? *(const uint32_t*)&qg[(size_t)r0 * HD + c]     : 0u;
        qf[kk][1] = (r1 < SS) ? *(const uint32_t*)&qg[(size_t)r1 * HD + c]     : 0u;
        qf[kk][2] = (r0 < SS) ? *(const uint32_t*)&qg[(size_t)r0 * HD + c + 8] : 0u;
        qf[kk][3] = (r1 < SS) ? *(const uint32_t*)&qg[(size_t)r1 * HD + c + 8] : 0u;
    }

    STAGE_KV(0, 0); STAGE_BIAS(0, 0);
    asm volatile("cp.async.commit_group;");

    float oacc[8][4];
    #pragma unroll
    for (int nf = 0; nf < 8; nf++)
        #pragma unroll
        for (int r = 0; r < 4; r++) oacc[nf][r] = 0.0f;
    float m0r = -CUDART_INF_F, m1r = -CUDART_INF_F, l0r = 0.0f, l1r = 0.0f;

    #pragma unroll 1
    for (int jt = 0; jt < 10; jt++) {
        const int j0 = jt * 64;
        const int buf = jt & 1;
        __syncthreads();                   // prev compute done; alt buffers free
        if (jt + 1 < 10) { STAGE_KV(jt + 1, buf ^ 1); STAGE_BIAS(jt + 1, buf ^ 1); }
        asm volatile("cp.async.commit_group;");
        asm volatile("cp.async.wait_group 1;");   // tile jt (K/V + bias) landed
        __syncthreads();

        const uint32_t kbase = s32 + (buf ? KB1 : KB0) + kfrag;
        const uint32_t vbase = s32 + (buf ? VB1 : VB0) + vfrag;
        const __half* bsm = (const __half*)(sh + (buf ? BB1 : BB0));

        // S = Q K^T
        float sacc[8][4];
        #pragma unroll
        for (int nf = 0; nf < 8; nf++)
            #pragma unroll
            for (int r = 0; r < 4; r++) sacc[nf][r] = 0.0f;
        #pragma unroll
        for (int kk = 0; kk < 4; kk++) {
            uint32_t bfr[8][2];
            #pragma unroll
            for (int p = 0; p < 4; p++)
                ldsm4(&bfr[2 * p][0], kbase + (uint32_t)(p * 16 * KSTH) * 2u + kk * 32u);
            #pragma unroll
            for (int nf = 0; nf < 8; nf++)
                mma_f16(sacc[nf], qf[kk], bfr[nf]);
        }

        // bias add (fp16 smem) + key mask + row max
        const __half* bb0 = &bsm[(wq * 16 + g) * KSTH + 2 * tg];
        const __half* bb1 = bb0 + 8 * KSTH;
        float mx0 = -CUDART_INF_F, mx1 = -CUDART_INF_F;
        #pragma unroll
        for (int nf = 0; nf < 8; nf++) {
            int col = j0 + nf * 8 + 2 * tg;
            float2 b0 = __half22float2(*(const __half2*)&bb0[nf * 8]);
            float2 b1 = __half22float2(*(const __half2*)&bb1[nf * 8]);
            sacc[nf][0] += b0.x; sacc[nf][1] += b0.y;
            sacc[nf][2] += b1.x; sacc[nf][3] += b1.y;
            if (col >= SS)     { sacc[nf][0] = -1e30f; sacc[nf][2] = -1e30f; }
            if (col + 1 >= SS) { sacc[nf][1] = -1e30f; sacc[nf][3] = -1e30f; }
            mx0 = fmaxf(mx0, fmaxf(sacc[nf][0], sacc[nf][1]));
            mx1 = fmaxf(mx1, fmaxf(sacc[nf][2], sacc[nf][3]));
        }
        mx0 = fmaxf(mx0, __shfl_xor_sync(0xffffffffu, mx0, 1));
        mx0 = fmaxf(mx0, __shfl_xor_sync(0xffffffffu, mx0, 2));
        mx1 = fmaxf(mx1, __shfl_xor_sync(0xffffffffu, mx1, 1));
        mx1 = fmaxf(mx1, __shfl_xor_sync(0xffffffffu, mx1, 2));

        float mn0 = fmaxf(m0r, mx0), mn1 = fmaxf(m1r, mx1);
        float corr0 = __expf(m0r - mn0), corr1 = __expf(m1r - mn1);
        m0r = mn0; m1r = mn1;

        float rs0 = 0.0f, rs1 = 0.0f;
        __half* pw0 = pp + (wq * 16 + g) * KSTH + 2 * tg;
        __half* pw1 = pw0 + 8 * KSTH;
        #pragma unroll
        for (int nf = 0; nf < 8; nf++) {
            float p0 = __expf(sacc[nf][0] - mn0);
            float p1 = __expf(sacc[nf][1] - mn0);
            float p2 = __expf(sacc[nf][2] - mn1);
            float p3 = __expf(sacc[nf][3] - mn1);
            rs0 += p0 + p1; rs1 += p2 + p3;
            *(uint32_t*)&pw0[nf * 8] = h2pack(p0, p1);
            *(uint32_t*)&pw1[nf * 8] = h2pack(p2, p3);
        }
        rs0 += __shfl_xor_sync(0xffffffffu, rs0, 1);
        rs0 += __shfl_xor_sync(0xffffffffu, rs0, 2);
        rs1 += __shfl_xor_sync(0xffffffffu, rs1, 1);
        rs1 += __shfl_xor_sync(0xffffffffu, rs1, 2);
        l0r = l0r * corr0 + rs0;
        l1r = l1r * corr1 + rs1;
        #pragma unroll
        for (int nf = 0; nf < 8; nf++) {
            oacc[nf][0] *= corr0; oacc[nf][1] *= corr0;
            oacc[nf][2] *= corr1; oacc[nf][3] *= corr1;
        }
        __syncwarp();   // P writes visible within warp (P rows are warp-private)

        // O += P V  (P A-frag ldmatrix; V B-frags ldmatrix.trans)
        #pragma unroll
        for (int kk = 0; kk < 4; kk++) {
            uint32_t af[4], bfv[8][2];
            ldsm4(af, pfoff + kk * 32u);
            #pragma unroll
            for (int p = 0; p < 4; p++)
                ldsm4t(&bfv[2 * p][0],
                       vbase + (uint32_t)(kk * 16 * KSTH) * 2u + p * 32u);
            #pragma unroll
            for (int nf = 0; nf < 8; nf++)
                mma_f16(oacc[nf], af, bfv[nf]);
        }
        __syncwarp();
    }

    float inv0 = 1.0f / l0r, inv1 = 1.0f / l1r;
    #pragma unroll
    for (int nf = 0; nf < 8; nf++) {
        int col = h * HD + nf * 8 + 2 * tg;
        if (r0 < SS) {
            float2 v = make_float2(oacc[nf][0] * inv0, oacc[nf][1] * inv0);
            *(float2*)&out[((size_t)b * SS + r0) * DD + col] = v;
        }
        if (r1 < SS) {
            float2 v = make_float2(oacc[nf][2] * inv1, oacc[nf][3] * inv1);
            *(float2*)&out[((size_t)b * SS + r1) * DD + col] = v;
        }
    }
}

// ---------------------------------------------------------------------------
extern "C" void kernel_launch(void* const* d_in, const int* in_sizes, int n_in,
                              void* d_out, int out_size)
{
    const float* X     = (const float*)d_in[0];
    const float* Wq    = (const float*)d_in[1];
    const float* bq    = (const float*)d_in[2];
    const float* Wk    = (const float*)d_in[3];
    const float* Wv    = (const float*)d_in[4];
    const float* bv    = (const float*)d_in[5];
    const float* table = (const float*)d_in[6];
    const int*   idx   = (const int*)d_in[7];
    float* out = (float*)d_out;

    cudaFuncSetAttribute(proj_mma_kernel, cudaFuncAttributeMaxDynamicSharedMemorySize, (int)PROJ_SMEM);
    cudaFuncSetAttribute(attn_kernel, cudaFuncAttributeMaxDynamicSharedMemorySize, (int)ATTN_SMEM);

    bias_kernel<<<(SS * SS + 255) / 256, 256>>>(table, idx);
    xhalf_kernel<<<(MTOT * DD / 4 + 255) / 256, 256>>>(X);
    transpose_w<<<dim3(DD/32, DD/32, 3), dim3(32, 8)>>>(Wq, Wk, Wv);
    proj_mma_kernel<<<dim3((MTOT + BM - 1) / BM, DD / BN, 3), 256, PROJ_SMEM>>>(bq, bv);
    attn_kernel<<<dim3(5, SB * HH), 256, ATTN_SMEM>>>(out);
}